// round 16
// baseline (speedup 1.0000x reference)
#include <cuda_runtime.h>

// Problem constants
#define NB 16
#define NS 128
#define NC 64
#define NH 8
#define NHD 64
#define ND 512
#define NM 256   // D/2

// k_preA role layout (42 blocks x 128 threads)
#define BID_SCAL 0
#define BID_P0 1
#define N_PBLK 16            // 32 rows of Ws each
#define BID_P0F 17           // p0 fold block
#define BID_G0 18
#define N_GBLK 16            // (h, m-half)
#define BID_F0 34
#define N_FBLK 8             // one per head h
#define GRID_PRE 42
#define N_MAIN (NB * NC)     // 1024

// ---------------- scratch (device globals; zero-initialized) ----------------
__device__ float g_sA[NH], g_sC[NH];
__device__ float g_R[ND], g_r0[ND];
__device__ float g_SR[NH], g_Rbe[NH];
__device__ float g_Sr0, g_r0be;
__device__ float g_Pp[N_PBLK * NM];
__device__ float g_p0q[N_PBLK * NM];
__device__ float g_p0[NM];
__device__ float g_G[NH * NM];
__device__ float g_g0p[NH * NM];
__device__ float g_B[NH * NH];
__device__ float g_b0p[NH * NH];
__device__ float g_Ap[NH], g_a0p[NH];
__device__ int   g_cs, g_cp, g_cp0, g_cg, g_cf;

__device__ __forceinline__ float warp_sum(float v) {
#pragma unroll
    for (int o = 16; o; o >>= 1) v += __shfl_xor_sync(0xffffffffu, v, o);
    return v;
}

__device__ __forceinline__ void spin_until(volatile int* ctr, int target) {
    while (*ctr < target) __nanosleep(64);
}

struct SmS { float accA[NH], accC[NH], accR[NH], accRbe[NH], accr0, accr0be; };
struct SmP { float sWv[32], sbv[32]; };
struct SmG { float sR[NHD], sr0[NHD]; };
struct SmF { float fred[4][18]; };

// =================== k_preA: all x-independent folding ======================
__global__ void __launch_bounds__(128) k_preA(
    const float* __restrict__ Wq, const float* __restrict__ bq,
    const float* __restrict__ Wk,
    const float* __restrict__ Wv, const float* __restrict__ bv,
    const float* __restrict__ Ws, const float* __restrict__ bs,
    const float* __restrict__ We, const float* __restrict__ be,
    const float* __restrict__ Wf)
{
    __shared__ union { SmS s; SmP p; SmG g; SmF f; } sm;
    int t = threadIdx.x;
    int bid = blockIdx.x;
    int lane = t & 31;
    int w = t >> 5;

    // ---- scalar block: sA/sC, R/r0, per-head sums ----
    if (bid == BID_SCAL) {
        if (t < NH) {
            sm.s.accA[t] = 0.f; sm.s.accC[t] = 0.f;
            sm.s.accR[t] = 0.f; sm.s.accRbe[t] = 0.f;
        }
        if (t == 0) { sm.s.accr0 = 0.f; sm.s.accr0be = 0.f; }
        __syncthreads();
#pragma unroll
        for (int seg = 0; seg < 4; seg++) {
            int d = t + seg * 128;
            float Rv  = Wv[d] * Wf[d];
            float r0v = bv[d] * Wf[d];
            float bev = be[d];
            g_R[d]  = Rv;
            g_r0[d] = r0v;
            float a   = warp_sum(Wq[d] * Wk[d]);
            float c   = warp_sum(bq[d] * Wk[d]);
            float rs  = warp_sum(Rv);
            float rbe = warp_sum(Rv * bev);
            float zs  = warp_sum(r0v);
            float zbe = warp_sum(r0v * bev);
            if (lane == 0) {
                int h = d >> 6;
                atomicAdd(&sm.s.accA[h], a);
                atomicAdd(&sm.s.accC[h], c);
                atomicAdd(&sm.s.accR[h], rs);
                atomicAdd(&sm.s.accRbe[h], rbe);
                atomicAdd(&sm.s.accr0, zs);
                atomicAdd(&sm.s.accr0be, zbe);
            }
        }
        __syncthreads();
        if (t < NH) {
            g_sA[t]  = sm.s.accA[t] * 0.125f;    // 1/sqrt(64)
            g_sC[t]  = sm.s.accC[t] * 0.125f;
            g_SR[t]  = sm.s.accR[t];
            g_Rbe[t] = sm.s.accRbe[t];
        }
        if (t == 0) { g_Sr0 = sm.s.accr0; g_r0be = sm.s.accr0be; }
        __threadfence();
        __syncthreads();
        if (t == 0) atomicAdd(&g_cs, 1);
        return;
    }

    // ---- P blocks (16 x 32 rows of Ws) ----
    if (bid < BID_P0F) {
        int pb = bid - BID_P0;
        int row0 = pb * 32;
        if (t < 32) {
            sm.p.sWv[t] = Wv[row0 + t];
            sm.p.sbv[t] = bv[row0 + t];
        }
        __syncthreads();
        float aP = 0.f, a0 = 0.f, bP = 0.f, b0 = 0.f;
        const float* wA = Ws + (size_t)row0 * NM + t;
        const float* wB = wA + 128;
#pragma unroll
        for (int r0i = 0; r0i < 32; r0i += 16) {
            float vA[16], vB[16];
#pragma unroll
            for (int u = 0; u < 16; u++) {
                vA[u] = wA[(size_t)(r0i + u) * NM];
                vB[u] = wB[(size_t)(r0i + u) * NM];
            }
#pragma unroll
            for (int u = 0; u < 16; u++) {
                float wvv = sm.p.sWv[r0i + u], bvv = sm.p.sbv[r0i + u];
                aP = fmaf(wvv, vA[u], aP);
                a0 = fmaf(bvv, vA[u], a0);
                bP = fmaf(wvv, vB[u], bP);
                b0 = fmaf(bvv, vB[u], b0);
            }
        }
        g_Pp[pb * NM + t]         = aP;
        g_p0q[pb * NM + t]        = a0;
        g_Pp[pb * NM + t + 128]   = bP;
        g_p0q[pb * NM + t + 128]  = b0;
        __threadfence();
        __syncthreads();
        if (t == 0) atomicAdd(&g_cp, 1);
        return;
    }

    // ---- p0 fold block ----
    if (bid == BID_P0F) {
        if (t == 0) spin_until(&g_cp, N_PBLK);
        __syncthreads();
        __threadfence();
#pragma unroll
        for (int half = 0; half < 2; half++) {
            int m = t + half * 128;
            float s = bs[m];
#pragma unroll
            for (int k = 0; k < N_PBLK; k++) s += g_p0q[k * NM + m];
            g_p0[m] = s;
        }
        __threadfence();
        __syncthreads();
        if (t == 0) atomicAdd(&g_cp0, 1);
        return;
    }

    // ---- G blocks (16: h = gb>>1, m-half = gb&1) ----
    if (bid < BID_F0) {
        int gb = bid - BID_G0;
        int h = gb >> 1;
        int m = (gb & 1) * 128 + t;
        if (t == 0) spin_until(&g_cs, 1);
        __syncthreads();
        __threadfence();
        if (t < NHD) {
            sm.g.sR[t]  = g_R[h * NHD + t];
            sm.g.sr0[t] = g_r0[h * NHD + t];
        }
        __syncthreads();
        const float* wp = We + (size_t)m * ND + h * NHD;
        float accG = 0.f, acc0 = 0.f;
#pragma unroll
        for (int d0 = 0; d0 < NHD; d0 += 16) {
            float v[16];
#pragma unroll
            for (int u = 0; u < 16; u++) v[u] = wp[d0 + u];
#pragma unroll
            for (int u = 0; u < 16; u++) {
                accG = fmaf(sm.g.sR[d0 + u], v[u], accG);
                acc0 = fmaf(sm.g.sr0[d0 + u], v[u], acc0);
            }
        }
        g_G[h * NM + m]   = accG;
        g_g0p[h * NM + m] = acc0;
        __threadfence();
        __syncthreads();
        if (t == 0) atomicAdd(&g_cg, 1);
        return;
    }

    // ---- F blocks (8, one per h): B, b0p, Ap, a0p; last one resets counters
    {
        int h = bid - BID_F0;
        if (t == 0) {
            spin_until(&g_cp, N_PBLK);
            spin_until(&g_cp0, 1);
            spin_until(&g_cg, N_GBLK);
        }
        __syncthreads();
        __threadfence();

        float acc[18];
#pragma unroll
        for (int i = 0; i < 18; i++) acc[i] = 0.f;

#pragma unroll
        for (int half = 0; half < 2; half++) {
            int m = t + half * 128;
            float Gv  = g_G[h * NM + m];
            float g0v = g_g0p[h * NM + m];
            float p0v = g_p0[m];
            float Pf[NH];
#pragma unroll
            for (int k = 0; k < NH; k++)
                Pf[k] = g_Pp[(2 * k) * NM + m] + g_Pp[(2 * k + 1) * NM + m];
#pragma unroll
            for (int k = 0; k < NH; k++) {
                acc[k]     = fmaf(Pf[k], Gv,  acc[k]);
                acc[8 + k] = fmaf(Pf[k], g0v, acc[8 + k]);
            }
            acc[16] = fmaf(p0v, Gv,  acc[16]);
            acc[17] = fmaf(p0v, g0v, acc[17]);
        }
#pragma unroll
        for (int i = 0; i < 18; i++) acc[i] = warp_sum(acc[i]);
        if (lane == 0) {
#pragma unroll
            for (int i = 0; i < 18; i++) sm.f.fred[w][i] = acc[i];
        }
        __syncthreads();
        if (t < 18) {
            float v = ((sm.f.fred[0][t] + sm.f.fred[1][t])
                     + (sm.f.fred[2][t] + sm.f.fred[3][t])) * 0.25f;
            if (t < 8)       g_B[h * NH + t] = v;
            else if (t < 16) g_b0p[h * NH + (t - 8)] = v;
            else if (t == 16) g_Ap[h] = v;
            else             g_a0p[h] = v;
        }
        __threadfence();
        __syncthreads();
        // F is the terminal stage: last F block resets all counters for the
        // next replay. All counter readers (G, p0F, F) have already passed.
        if (t == 0) {
            int v = atomicAdd(&g_cf, 1);
            if (v == N_FBLK - 1) {
                g_cs = 0; g_cp = 0; g_cp0 = 0; g_cg = 0; g_cf = 0;
            }
        }
    }
}

// =================== k_main: pure compute, zero inter-block sync ============
__global__ void __launch_bounds__(128) k_main(
    const float* __restrict__ x,
    const float* __restrict__ bf,
    float* __restrict__ out)
{
    __shared__ float xs[NS];
    __shared__ float xv[NH][NS];
    __shared__ float sqv[NH], w1s[NH];
    __shared__ float w0s;

    int t = threadIdx.x;
    int lane = t & 31;
    int w = t >> 5;
    int c = blockIdx.x & (NC - 1);
    int b = blockIdx.x >> 6;

    xs[t] = x[((size_t)(b * NS + t)) * NC + c];
    __syncthreads();

    float x0 = xs[lane];
    float x1 = xs[lane + 32];
    float x2 = xs[lane + 64];
    float x3 = xs[lane + 96];

    // raw power sums M1..M7 (per warp, redundant across warps)
    float s1 = 0.f, s2 = 0.f, s3 = 0.f, s4 = 0.f, s5 = 0.f, s6 = 0.f, s7 = 0.f;
#define POWSTEP(xk) do { float p = (xk); s1 += p; p *= (xk); s2 += p; \
    p *= (xk); s3 += p; p *= (xk); s4 += p; p *= (xk); s5 += p; \
    p *= (xk); s6 += p; p *= (xk); s7 += p; } while (0)
    POWSTEP(x0); POWSTEP(x1); POWSTEP(x2); POWSTEP(x3);
#undef POWSTEP
    s1 = warp_sum(s1); s2 = warp_sum(s2); s3 = warp_sum(s3);
    s4 = warp_sum(s4); s5 = warp_sum(s5); s6 = warp_sum(s6);
    s7 = warp_sum(s7);

    const float i2 = 0.5f, i3 = 1.f/6.f, i4 = 1.f/24.f, i5 = 1.f/120.f, i6 = 1.f/720.f;
    float cd0 = 128.f,   cd1 = s1,      cd2 = s2 * i2, cd3 = s3 * i3,
          cd4 = s4 * i4, cd5 = s5 * i5, cd6 = s6 * i6;
    float cn0 = s1,      cn1 = s2,      cn2 = s3 * i2, cn3 = s4 * i3,
          cn4 = s5 * i4, cn5 = s6 * i5, cn6 = s7 * i6;

    // two heads per warp: rational evaluation + squeeze
#pragma unroll
    for (int hh = 0; hh < 2; hh++) {
        int h = 2 * w + hh;
        float sa = g_sA[h], scc = g_sC[h];
        float f0, f1, f2, f3;
#define HORNER(xq, fout) do { \
        float bb = fmaf(sa, (xq), scc); \
        float num = fmaf(cn6, bb, cn5); num = fmaf(num, bb, cn4); \
        num = fmaf(num, bb, cn3); num = fmaf(num, bb, cn2); \
        num = fmaf(num, bb, cn1); num = fmaf(num, bb, cn0); \
        float den = fmaf(cd6, bb, cd5); den = fmaf(den, bb, cd4); \
        den = fmaf(den, bb, cd3); den = fmaf(den, bb, cd2); \
        den = fmaf(den, bb, cd1); den = fmaf(den, bb, cd0); \
        fout = __fdividef(num, den); } while (0)
        HORNER(x0, f0); HORNER(x1, f1); HORNER(x2, f2); HORNER(x3, f3);
#undef HORNER
        xv[h][lane]      = f0;
        xv[h][lane + 32] = f1;
        xv[h][lane + 64] = f2;
        xv[h][lane + 96] = f3;
        float s = warp_sum(((f0 + f1) + f2) + f3);
        if (lane == 0) sqv[h] = s * (1.0f / NS);
    }
    __syncthreads();

    // warp 0: w1[h] = A-terms + B[h][:]·sqv ; w0 = a0-terms + b0·sqv
    if (w == 0) {
        float sq[NH];
#pragma unroll
        for (int k = 0; k < NH; k++) sq[k] = sqv[k];
        float w0p = 0.f;
        if (lane < NH) {
            int h = lane;
            float w1v = g_SR[h] * 0.5f + g_Rbe[h] * 0.25f + g_Ap[h];
            w0p = g_a0p[h];
#pragma unroll
            for (int k = 0; k < NH; k++) {
                w1v = fmaf(sq[k], g_B[h * NH + k], w1v);
                w0p = fmaf(sq[k], g_b0p[h * NH + k], w0p);
            }
            w1s[h] = w1v;
        }
        w0p = warp_sum(w0p);               // lanes >= 8 contribute 0
        if (lane == 0)
            w0s = w0p + g_Sr0 * 0.5f + g_r0be * 0.25f + bf[0];
    }
    __syncthreads();

    // final: thread t -> timestep t
    float o = w0s;
#pragma unroll
    for (int h = 0; h < NH; h++)
        o = fmaf(xv[h][t], w1s[h], o);
    out[((size_t)(b * NS + t)) * NC + c] = o;
}

// ---------------- launch ----------------------------------------------------
extern "C" void kernel_launch(void* const* d_in, const int* in_sizes, int n_in,
                              void* d_out, int out_size)
{
    const float* x  = (const float*)d_in[0];
    const float* Wq = (const float*)d_in[1];
    const float* bq = (const float*)d_in[2];
    const float* Wk = (const float*)d_in[3];
    // d_in[4] = bk: cancels under softmax, unused
    const float* Wv = (const float*)d_in[5];
    const float* bv = (const float*)d_in[6];
    const float* Ws = (const float*)d_in[7];
    const float* bs = (const float*)d_in[8];
    const float* We = (const float*)d_in[9];
    const float* be = (const float*)d_in[10];
    const float* Wf = (const float*)d_in[11];
    const float* bf = (const float*)d_in[12];
    float* out = (float*)d_out;

    k_preA<<<GRID_PRE, 128>>>(Wq, bq, Wk, Wv, bv, Ws, bs, We, be, Wf);
    k_main<<<N_MAIN, 128>>>(x, bf, out);
}

// round 17
// speedup vs baseline: 1.2245x; 1.2245x over previous
#include <cuda_runtime.h>

// Problem constants
#define NB 16
#define NS 128
#define NC 64
#define NH 8
#define NHD 64
#define ND 512
#define NM 256   // D/2

// k_pre1 layout: 33 blocks x 128 (scal=0, P=1..16, G=17..32), zero spins
#define BID_SCAL 0
#define BID_P0 1
#define N_PBLK 16
#define BID_G0 17
#define N_GBLK 16
#define GRID_PRE1 33
#define N_FBLK 8
#define N_MAIN (NB * NC)     // 1024

// ---------------- scratch (device globals) ----------------------------------
__device__ float g_sA[NH], g_sC[NH];
__device__ float g_SR[NH], g_Rbe[NH];
__device__ float g_Sr0, g_r0be;
__device__ float g_Pp[N_PBLK * NM];     // P partials per 32-row chunk
__device__ float g_p0q[N_PBLK * NM];    // p0 partials (bv @ Ws)
__device__ float g_G[NH * NM];          // G[h][m] = sum_{d in h} (Wv*Wf)[d] We[m][d]
__device__ float g_g0p[NH * NM];        // same with bv*Wf
__device__ float g_B[NH * NH];
__device__ float g_b0p[NH * NH];
__device__ float g_Ap[NH], g_a0p[NH];

__device__ __forceinline__ float warp_sum(float v) {
#pragma unroll
    for (int o = 16; o; o >>= 1) v += __shfl_xor_sync(0xffffffffu, v, o);
    return v;
}

struct SmS { float accA[NH], accC[NH], accR[NH], accRbe[NH], accr0, accr0be; };
struct SmP { float sWv[32], sbv[32]; };
struct SmG { float sR[NHD], sr0[NHD]; };
struct SmF { float fred[4][18]; };

// =================== k_pre1: scal + P + G, all independent ==================
__global__ void __launch_bounds__(128) k_pre1(
    const float* __restrict__ Wq, const float* __restrict__ bq,
    const float* __restrict__ Wk,
    const float* __restrict__ Wv, const float* __restrict__ bv,
    const float* __restrict__ Ws,
    const float* __restrict__ We, const float* __restrict__ be,
    const float* __restrict__ Wf)
{
    __shared__ union { SmS s; SmP p; SmG g; } sm;
    int t = threadIdx.x;
    int bid = blockIdx.x;
    int lane = t & 31;

    // ---- scalar block: sA/sC + per-head R/r0 sums --------------------------
    if (bid == BID_SCAL) {
        if (t < NH) {
            sm.s.accA[t] = 0.f; sm.s.accC[t] = 0.f;
            sm.s.accR[t] = 0.f; sm.s.accRbe[t] = 0.f;
        }
        if (t == 0) { sm.s.accr0 = 0.f; sm.s.accr0be = 0.f; }
        __syncthreads();
#pragma unroll
        for (int seg = 0; seg < 4; seg++) {
            int d = t + seg * 128;             // each warp covers one half-head
            float Rv  = Wv[d] * Wf[d];
            float r0v = bv[d] * Wf[d];
            float bev = be[d];
            float a   = warp_sum(Wq[d] * Wk[d]);
            float c   = warp_sum(bq[d] * Wk[d]);
            float rs  = warp_sum(Rv);
            float rbe = warp_sum(Rv * bev);
            float zs  = warp_sum(r0v);
            float zbe = warp_sum(r0v * bev);
            if (lane == 0) {
                int h = d >> 6;
                atomicAdd(&sm.s.accA[h], a);
                atomicAdd(&sm.s.accC[h], c);
                atomicAdd(&sm.s.accR[h], rs);
                atomicAdd(&sm.s.accRbe[h], rbe);
                atomicAdd(&sm.s.accr0, zs);
                atomicAdd(&sm.s.accr0be, zbe);
            }
        }
        __syncthreads();
        if (t < NH) {
            g_sA[t]  = sm.s.accA[t] * 0.125f;   // 1/sqrt(64)
            g_sC[t]  = sm.s.accC[t] * 0.125f;
            g_SR[t]  = sm.s.accR[t];
            g_Rbe[t] = sm.s.accRbe[t];
        }
        if (t == 0) { g_Sr0 = sm.s.accr0; g_r0be = sm.s.accr0be; }
        return;
    }

    // ---- P blocks (16 x 32 rows of Ws) -------------------------------------
    if (bid < BID_G0) {
        int pb = bid - BID_P0;
        int row0 = pb * 32;
        if (t < 32) {
            sm.p.sWv[t] = Wv[row0 + t];
            sm.p.sbv[t] = bv[row0 + t];
        }
        __syncthreads();
        float aP = 0.f, a0 = 0.f, bP = 0.f, b0 = 0.f;
        const float* wA = Ws + (size_t)row0 * NM + t;
        const float* wB = wA + 128;
#pragma unroll
        for (int r0i = 0; r0i < 32; r0i += 16) {
            float vA[16], vB[16];
#pragma unroll
            for (int u = 0; u < 16; u++) {
                vA[u] = wA[(size_t)(r0i + u) * NM];
                vB[u] = wB[(size_t)(r0i + u) * NM];
            }
#pragma unroll
            for (int u = 0; u < 16; u++) {
                float wvv = sm.p.sWv[r0i + u], bvv = sm.p.sbv[r0i + u];
                aP = fmaf(wvv, vA[u], aP);
                a0 = fmaf(bvv, vA[u], a0);
                bP = fmaf(wvv, vB[u], bP);
                b0 = fmaf(bvv, vB[u], b0);
            }
        }
        g_Pp[pb * NM + t]         = aP;
        g_p0q[pb * NM + t]        = a0;
        g_Pp[pb * NM + t + 128]   = bP;
        g_p0q[pb * NM + t + 128]  = b0;
        return;
    }

    // ---- G blocks (16: h = gb>>1, m-half = gb&1); R computed inline --------
    {
        int gb = bid - BID_G0;
        int h = gb >> 1;
        int m = (gb & 1) * 128 + t;
        if (t < NHD) {
            int d = h * NHD + t;
            sm.g.sR[t]  = Wv[d] * Wf[d];       // R inline (no dependency)
            sm.g.sr0[t] = bv[d] * Wf[d];
        }
        __syncthreads();
        const float* wp = We + (size_t)m * ND + h * NHD;
        float accG = 0.f, acc0 = 0.f;
#pragma unroll
        for (int d0 = 0; d0 < NHD; d0 += 16) {
            float v[16];
#pragma unroll
            for (int u = 0; u < 16; u++) v[u] = wp[d0 + u];
#pragma unroll
            for (int u = 0; u < 16; u++) {
                accG = fmaf(sm.g.sR[d0 + u], v[u], accG);
                acc0 = fmaf(sm.g.sr0[d0 + u], v[u], acc0);
            }
        }
        g_G[h * NM + m]   = accG;
        g_g0p[h * NM + m] = acc0;
    }
}

// =================== k_pre2: 8 F blocks, p0 folded inline ===================
__global__ void __launch_bounds__(128) k_pre2(
    const float* __restrict__ bs)
{
    __shared__ SmF smf;
    int t = threadIdx.x;
    int h = blockIdx.x;
    int lane = t & 31;
    int w = t >> 5;

    float acc[18];                 // 0-7 B[h][k], 8-15 b0p[h][k], 16 Ap, 17 a0p
#pragma unroll
    for (int i = 0; i < 18; i++) acc[i] = 0.f;

#pragma unroll
    for (int half = 0; half < 2; half++) {
        int m = t + half * 128;
        float Gv  = g_G[h * NM + m];
        float g0v = g_g0p[h * NM + m];
        // p0 folded inline, same order as before (bs + k ascending)
        float p0v = bs[m];
#pragma unroll
        for (int k = 0; k < N_PBLK; k++) p0v += g_p0q[k * NM + m];
        float Pf[NH];
#pragma unroll
        for (int k = 0; k < NH; k++)
            Pf[k] = g_Pp[(2 * k) * NM + m] + g_Pp[(2 * k + 1) * NM + m];
#pragma unroll
        for (int k = 0; k < NH; k++) {
            acc[k]     = fmaf(Pf[k], Gv,  acc[k]);
            acc[8 + k] = fmaf(Pf[k], g0v, acc[8 + k]);
        }
        acc[16] = fmaf(p0v, Gv,  acc[16]);
        acc[17] = fmaf(p0v, g0v, acc[17]);
    }
#pragma unroll
    for (int i = 0; i < 18; i++) acc[i] = warp_sum(acc[i]);
    if (lane == 0) {
#pragma unroll
        for (int i = 0; i < 18; i++) smf.fred[w][i] = acc[i];
    }
    __syncthreads();
    if (t < 18) {
        float v = ((smf.fred[0][t] + smf.fred[1][t])
                 + (smf.fred[2][t] + smf.fred[3][t])) * 0.25f;
        if (t < 8)        g_B[h * NH + t] = v;
        else if (t < 16)  g_b0p[h * NH + (t - 8)] = v;
        else if (t == 16) g_Ap[h] = v;
        else              g_a0p[h] = v;
    }
}

// =================== k_main: pure compute, zero inter-block sync ============
__global__ void __launch_bounds__(128) k_main(
    const float* __restrict__ x,
    const float* __restrict__ bf,
    float* __restrict__ out)
{
    __shared__ float xs[NS];
    __shared__ float xv[NH][NS];
    __shared__ float sqv[NH], w1s[NH];
    __shared__ float w0s;

    int t = threadIdx.x;
    int lane = t & 31;
    int w = t >> 5;
    int c = blockIdx.x & (NC - 1);
    int b = blockIdx.x >> 6;

    xs[t] = x[((size_t)(b * NS + t)) * NC + c];
    __syncthreads();

    float x0 = xs[lane];
    float x1 = xs[lane + 32];
    float x2 = xs[lane + 64];
    float x3 = xs[lane + 96];

    // raw power sums M1..M7 (per warp, redundant across warps)
    float s1 = 0.f, s2 = 0.f, s3 = 0.f, s4 = 0.f, s5 = 0.f, s6 = 0.f, s7 = 0.f;
#define POWSTEP(xk) do { float p = (xk); s1 += p; p *= (xk); s2 += p; \
    p *= (xk); s3 += p; p *= (xk); s4 += p; p *= (xk); s5 += p; \
    p *= (xk); s6 += p; p *= (xk); s7 += p; } while (0)
    POWSTEP(x0); POWSTEP(x1); POWSTEP(x2); POWSTEP(x3);
#undef POWSTEP
    s1 = warp_sum(s1); s2 = warp_sum(s2); s3 = warp_sum(s3);
    s4 = warp_sum(s4); s5 = warp_sum(s5); s6 = warp_sum(s6);
    s7 = warp_sum(s7);

    const float i2 = 0.5f, i3 = 1.f/6.f, i4 = 1.f/24.f, i5 = 1.f/120.f, i6 = 1.f/720.f;
    float cd0 = 128.f,   cd1 = s1,      cd2 = s2 * i2, cd3 = s3 * i3,
          cd4 = s4 * i4, cd5 = s5 * i5, cd6 = s6 * i6;
    float cn0 = s1,      cn1 = s2,      cn2 = s3 * i2, cn3 = s4 * i3,
          cn4 = s5 * i4, cn5 = s6 * i5, cn6 = s7 * i6;

    // two heads per warp: rational evaluation + squeeze
#pragma unroll
    for (int hh = 0; hh < 2; hh++) {
        int h = 2 * w + hh;
        float sa = g_sA[h], scc = g_sC[h];
        float f0, f1, f2, f3;
#define HORNER(xq, fout) do { \
        float bb = fmaf(sa, (xq), scc); \
        float num = fmaf(cn6, bb, cn5); num = fmaf(num, bb, cn4); \
        num = fmaf(num, bb, cn3); num = fmaf(num, bb, cn2); \
        num = fmaf(num, bb, cn1); num = fmaf(num, bb, cn0); \
        float den = fmaf(cd6, bb, cd5); den = fmaf(den, bb, cd4); \
        den = fmaf(den, bb, cd3); den = fmaf(den, bb, cd2); \
        den = fmaf(den, bb, cd1); den = fmaf(den, bb, cd0); \
        fout = __fdividef(num, den); } while (0)
        HORNER(x0, f0); HORNER(x1, f1); HORNER(x2, f2); HORNER(x3, f3);
#undef HORNER
        xv[h][lane]      = f0;
        xv[h][lane + 32] = f1;
        xv[h][lane + 64] = f2;
        xv[h][lane + 96] = f3;
        float s = warp_sum(((f0 + f1) + f2) + f3);
        if (lane == 0) sqv[h] = s * (1.0f / NS);
    }
    __syncthreads();

    // warp 0: w1[h] = A-terms + B[h][:]·sqv ; w0 = a0-terms + b0·sqv
    if (w == 0) {
        float sq[NH];
#pragma unroll
        for (int k = 0; k < NH; k++) sq[k] = sqv[k];
        float w0p = 0.f;
        if (lane < NH) {
            int h = lane;
            float w1v = g_SR[h] * 0.5f + g_Rbe[h] * 0.25f + g_Ap[h];
            w0p = g_a0p[h];
#pragma unroll
            for (int k = 0; k < NH; k++) {
                w1v = fmaf(sq[k], g_B[h * NH + k], w1v);
                w0p = fmaf(sq[k], g_b0p[h * NH + k], w0p);
            }
            w1s[h] = w1v;
        }
        w0p = warp_sum(w0p);               // lanes >= 8 contribute 0
        if (lane == 0)
            w0s = w0p + g_Sr0 * 0.5f + g_r0be * 0.25f + bf[0];
    }
    __syncthreads();

    // final: thread t -> timestep t
    float o = w0s;
#pragma unroll
    for (int h = 0; h < NH; h++)
        o = fmaf(xv[h][t], w1s[h], o);
    out[((size_t)(b * NS + t)) * NC + c] = o;
}

// ---------------- launch ----------------------------------------------------
extern "C" void kernel_launch(void* const* d_in, const int* in_sizes, int n_in,
                              void* d_out, int out_size)
{
    const float* x  = (const float*)d_in[0];
    const float* Wq = (const float*)d_in[1];
    const float* bq = (const float*)d_in[2];
    const float* Wk = (const float*)d_in[3];
    // d_in[4] = bk: cancels under softmax, unused
    const float* Wv = (const float*)d_in[5];
    const float* bv = (const float*)d_in[6];
    const float* Ws = (const float*)d_in[7];
    const float* bs = (const float*)d_in[8];
    const float* We = (const float*)d_in[9];
    const float* be = (const float*)d_in[10];
    const float* Wf = (const float*)d_in[11];
    const float* bf = (const float*)d_in[12];
    float* out = (float*)d_out;

    k_pre1<<<GRID_PRE1, 128>>>(Wq, bq, Wk, Wv, bv, Ws, We, be, Wf);
    k_pre2<<<N_FBLK, 128>>>(bs);
    k_main<<<N_MAIN, 128>>>(x, bf, out);
}